// round 1
// baseline (speedup 1.0000x reference)
#include <cuda_runtime.h>
#include <cstdint>

// ColorHistogramLoss — soft 64-bin histogram CDF L1 loss.
// Strategy: moment-compressed binning (count + first moment per 1/32-bin
// subcell, packed into one u64 shared atomic per pixel), then a tiny
// table-driven gather reconstructs the exact soft histogram to ~1e-6
// relative accuracy, followed by cdf + mean|diff| in double.

namespace chl {

constexpr int BINS   = 64;
constexpr int TSUB   = 32;              // subcells per bin
constexpr int NSUB   = BINS * TSUB;     // 2048 subcells over [0,1)
constexpr int NCH    = 12;              // B*C
constexpr int NIMG   = 24;              // 2 tensors * 12 channels
constexpr int PIX    = 65536;           // H*W
constexpr int SLICES = 16;
constexpr int PIX_BLK = PIX / SLICES;   // 4096
constexpr int THR    = 256;
constexpr int WSUP   = 416;             // kernel support in subcells (|d|<=6.5 bins)

__device__ unsigned long long g_acc[NIMG * NSUB];  // packed (cnt<<40)|sum(f*2^20)
__device__ double g_hist[NIMG * BINS];

__global__ void k_zero() {
  int i = blockIdx.x * blockDim.x + threadIdx.x;
  if (i < NIMG * NSUB) g_acc[i] = 0ULL;
}

__global__ void __launch_bounds__(THR) k_bin(const float* __restrict__ pred,
                                             const float* __restrict__ tgt) {
  __shared__ unsigned long long sh[NSUB];
  int blk   = blockIdx.x;
  int img   = blk / SLICES;             // 0..23
  int slice = blk % SLICES;
  const float* src = (img < NCH ? pred : tgt) + (img % NCH) * PIX + slice * PIX_BLK;

  for (int i = threadIdx.x; i < NSUB; i += THR) sh[i] = 0ULL;
  __syncthreads();

  const float4* p4 = reinterpret_cast<const float4*>(src);
#pragma unroll
  for (int it = 0; it < PIX_BLK / 4 / THR; ++it) {
    float4 v = p4[it * THR + threadIdx.x];
    float xs[4] = {v.x, v.y, v.z, v.w};
#pragma unroll
    for (int k = 0; k < 4; ++k) {
      float su = xs[k] * 2048.0f;          // exact: power-of-2 scale
      int s = (int)su;
      s = max(0, min(NSUB - 1, s));
      float f = su - (float)s;             // in-cell position, [0,1)
      unsigned q = (unsigned)__float2int_rn(f * 1048576.0f);  // f*2^20, <= 2^20
      atomicAdd(&sh[s], (1ULL << 40) | (unsigned long long)q);
    }
  }
  __syncthreads();

  unsigned long long* g = g_acc + img * NSUB;
  for (int i = threadIdx.x; i < NSUB; i += THR) {
    unsigned long long v = sh[i];
    if (v) atomicAdd(&g[i], v);
  }
}

// Per-channel soft histogram from subcell moments.
// d(s,j) = (s + 0.5)/32 - (j + 0.5)  (bin units), support |d| <= ~6.5.
// hist[j] = sum_s  cnt_s * exp(-d^2/2)  +  sumdelta_s * (1/32) * (-d) exp(-d^2/2)
__global__ void __launch_bounds__(256) k_hist() {
  __shared__ float Wt[WSUP], Wpt[WSUP];
  __shared__ float cnt_sh[NSUB], sd_sh[NSUB];
  int img = blockIdx.x;

  for (int o = threadIdx.x; o < WSUP; o += 256) {
    double d = (o - 207.5) * (1.0 / 32.0);
    double w = exp(-0.5 * d * d);
    Wt[o]  = (float)w;
    Wpt[o] = (float)(-d * w * (1.0 / 32.0));
  }
  const unsigned long long* g = g_acc + img * NSUB;
  for (int i = threadIdx.x; i < NSUB; i += 256) {
    unsigned long long v = g[i];
    double cnt = (double)(v >> 40);
    double lo  = (double)(v & ((1ULL << 40) - 1ULL));
    cnt_sh[i] = (float)cnt;
    sd_sh[i]  = (float)(lo * 0x1p-20 - cnt * 0.5);  // sum of (f - 0.5)
  }
  __syncthreads();

  int j    = threadIdx.x >> 2;   // bin 0..63
  int part = threadIdx.x & 3;
  double acc = 0.0;
  int sbase = TSUB * j - 192;    // s = sbase + o
  for (int o = part; o < WSUP; o += 4) {
    int s = sbase + o;
    if ((unsigned)s < (unsigned)NSUB)
      acc += (double)cnt_sh[s] * (double)Wt[o] + (double)sd_sh[s] * (double)Wpt[o];
  }
  acc += __shfl_down_sync(0xffffffffu, acc, 1);
  acc += __shfl_down_sync(0xffffffffu, acc, 2);
  if (part == 0) g_hist[img * BINS + j] = acc;
}

// cdf per channel (warp scan over 64 bins, 2 per lane) + mean |cdf_p - cdf_t|.
__global__ void __launch_bounds__(768) k_final(float* __restrict__ out) {
  __shared__ double cdf[NIMG][BINS];
  __shared__ double red[24];
  int warp = threadIdx.x >> 5;
  int lane = threadIdx.x & 31;

  {
    int img = warp;  // 24 warps == 24 channel-images
    double p0 = g_hist[img * BINS + lane];
    double p1 = g_hist[img * BINS + 32 + lane];
#pragma unroll
    for (int d = 1; d < 32; d <<= 1) {
      double t0 = __shfl_up_sync(0xffffffffu, p0, d);
      double t1 = __shfl_up_sync(0xffffffffu, p1, d);
      if (lane >= d) { p0 += t0; p1 += t1; }
    }
    double half0 = __shfl_sync(0xffffffffu, p0, 31);
    double total = half0 + __shfl_sync(0xffffffffu, p1, 31);
    double denom = total + 1e-8;
    cdf[img][lane]      = p0 / denom;
    cdf[img][lane + 32] = (half0 + p1) / denom;
  }
  __syncthreads();

  double s;
  {
    int ch = threadIdx.x >> 6;     // 0..11
    int j  = threadIdx.x & 63;
    s = fabs(cdf[ch][j] - cdf[ch + NCH][j]);
  }
#pragma unroll
  for (int d = 16; d; d >>= 1) s += __shfl_down_sync(0xffffffffu, s, d);
  if (lane == 0) red[warp] = s;
  __syncthreads();
  if (threadIdx.x == 0) {
    double tot = 0.0;
    for (int w = 0; w < 24; ++w) tot += red[w];
    out[0] = (float)(tot / 768.0);
  }
}

}  // namespace chl

extern "C" void kernel_launch(void* const* d_in, const int* in_sizes, int n_in,
                              void* d_out, int out_size) {
  const float* pred = (const float*)d_in[0];
  const float* tgt  = (const float*)d_in[1];
  float* out = (float*)d_out;

  chl::k_zero<<<(chl::NIMG * chl::NSUB + 255) / 256, 256>>>();
  chl::k_bin<<<chl::NIMG * chl::SLICES, chl::THR>>>(pred, tgt);
  chl::k_hist<<<chl::NIMG, 256>>>();
  chl::k_final<<<1, 768>>>(out);
}

// round 2
// speedup vs baseline: 3.2989x; 3.2989x over previous
#include <cuda_runtime.h>
#include <cstdint>

// ColorHistogramLoss — soft 64-bin histogram CDF L1 loss.
// R2: all-fp32 downstream, fused hist+final via last-block ticket,
// k_zero eliminated (hist blocks re-zero their g_acc slice; module-load
// zero-init covers the very first call). 2 kernels total.

namespace chl {

constexpr int BINS    = 64;
constexpr int TSUB    = 32;              // subcells per bin
constexpr int NSUB    = BINS * TSUB;     // 2048 subcells over [0,1)
constexpr int NCH     = 12;              // B*C
constexpr int NIMG    = 24;              // 2 tensors * 12 channels
constexpr int PIX     = 65536;           // H*W
constexpr int SLICES  = 16;
constexpr int PIX_BLK = PIX / SLICES;    // 4096
constexpr int THR     = 256;
constexpr int WSUP    = 416;             // kernel support in subcells (|d|<=6.5 bins)

__device__ unsigned long long g_acc[NIMG * NSUB];  // packed (cnt<<40)|sum(f*2^20); zero-init
__device__ float g_histf[NIMG * BINS];
__device__ int   g_count;                           // zero-init; reset by last block

__global__ void __launch_bounds__(THR) k_bin(const float* __restrict__ pred,
                                             const float* __restrict__ tgt) {
  __shared__ unsigned long long sh[NSUB];
  int blk   = blockIdx.x;
  int img   = blk / SLICES;             // 0..23
  int slice = blk % SLICES;
  const float* src = (img < NCH ? pred : tgt) + (img % NCH) * PIX + slice * PIX_BLK;

  for (int i = threadIdx.x; i < NSUB; i += THR) sh[i] = 0ULL;
  __syncthreads();

  const float4* p4 = reinterpret_cast<const float4*>(src);
#pragma unroll
  for (int it = 0; it < PIX_BLK / 4 / THR; ++it) {
    float4 v = p4[it * THR + threadIdx.x];
    float xs[4] = {v.x, v.y, v.z, v.w};
#pragma unroll
    for (int k = 0; k < 4; ++k) {
      float su = xs[k] * 2048.0f;          // exact: power-of-2 scale
      int s = (int)su;
      s = max(0, min(NSUB - 1, s));
      float f = su - (float)s;             // in-cell position, [0,1)
      unsigned q = (unsigned)__float2int_rn(f * 1048576.0f);  // f*2^20
      atomicAdd(&sh[s], (1ULL << 40) | (unsigned long long)q);
    }
  }
  __syncthreads();

  unsigned long long* g = g_acc + img * NSUB;
  for (int i = threadIdx.x; i < NSUB; i += THR) {
    unsigned long long v = sh[i];
    if (v) atomicAdd(&g[i], v);
  }
}

// Per-channel soft histogram from subcell moments (fp32), then the LAST
// block to finish computes cdfs + mean |diff| for everything.
// d(s,j) = (s + 0.5)/32 - (j + 0.5)  (bin units), support |d| <= 6.5.
// hist[j] = sum_s  cnt_s * exp(-d^2/2)  +  sumdelta_s * (1/32)*(-d)exp(-d^2/2)
__global__ void __launch_bounds__(256) k_histfinal(float* __restrict__ out) {
  __shared__ float Wt[WSUP], Wpt[WSUP];
  __shared__ float cnt_sh[NSUB], sd_sh[NSUB];
  __shared__ float cdf_sh[NIMG][BINS];
  __shared__ float red_sh[8];
  __shared__ int ticket_sh;
  int tid = threadIdx.x;
  int img = blockIdx.x;

  for (int o = tid; o < WSUP; o += 256) {
    float d = ((float)o - 207.5f) * (1.0f / 32.0f);
    float w = __expf(-0.5f * d * d);
    Wt[o]  = w;
    Wpt[o] = -d * w * (1.0f / 32.0f);
  }
  unsigned long long* g = g_acc + img * NSUB;
  for (int i = tid; i < NSUB; i += 256) {
    unsigned long long v = g[i];
    g[i] = 0ULL;                                   // re-zero for next replay
    float cnt = (float)(unsigned)(v >> 40);
    float lo  = (float)(v & ((1ULL << 40) - 1ULL));
    cnt_sh[i] = cnt;
    sd_sh[i]  = lo * 0x1p-20f - cnt * 0.5f;        // sum of (f - 0.5)
  }
  __syncthreads();

  int j    = tid >> 2;          // bin 0..63
  int part = tid & 3;
  float acc = 0.0f;
  int sbase = TSUB * j - 192;   // s = sbase + o
  for (int o = part; o < WSUP; o += 4) {
    int s = sbase + o;
    if ((unsigned)s < (unsigned)NSUB)
      acc = fmaf(cnt_sh[s], Wt[o], fmaf(sd_sh[s], Wpt[o], acc));
  }
  acc += __shfl_down_sync(0xffffffffu, acc, 1);
  acc += __shfl_down_sync(0xffffffffu, acc, 2);
  if (part == 0) g_histf[img * BINS + j] = acc;

  // --- last-block-done ticket ---
  __threadfence();
  __syncthreads();
  if (tid == 0) ticket_sh = atomicAdd(&g_count, 1);
  __syncthreads();
  if (ticket_sh != NIMG - 1) return;

  // last block: finalize
  __threadfence();
  if (tid == 0) g_count = 0;    // reset for next replay

  int warp = tid >> 5, lane = tid & 31;   // 8 warps
  for (int im = warp; im < NIMG; im += 8) {
    float p0 = g_histf[im * BINS + lane];
    float p1 = g_histf[im * BINS + 32 + lane];
#pragma unroll
    for (int d = 1; d < 32; d <<= 1) {
      float t0 = __shfl_up_sync(0xffffffffu, p0, d);
      float t1 = __shfl_up_sync(0xffffffffu, p1, d);
      if (lane >= d) { p0 += t0; p1 += t1; }
    }
    float half0 = __shfl_sync(0xffffffffu, p0, 31);
    float inv   = __frcp_rn(half0 + __shfl_sync(0xffffffffu, p1, 31) + 1e-8f);
    cdf_sh[im][lane]      = p0 * inv;
    cdf_sh[im][lane + 32] = (half0 + p1) * inv;
  }
  __syncthreads();

  float s = 0.0f;
  for (int i = tid; i < NCH * BINS; i += 256) {
    int ch = i >> 6, jj = i & 63;
    s += fabsf(cdf_sh[ch][jj] - cdf_sh[ch + NCH][jj]);
  }
#pragma unroll
  for (int d = 16; d; d >>= 1) s += __shfl_down_sync(0xffffffffu, s, d);
  if (lane == 0) red_sh[warp] = s;
  __syncthreads();
  if (tid == 0) {
    float tot = 0.0f;
#pragma unroll
    for (int w = 0; w < 8; ++w) tot += red_sh[w];
    out[0] = tot / (float)(NCH * BINS);
  }
}

}  // namespace chl

extern "C" void kernel_launch(void* const* d_in, const int* in_sizes, int n_in,
                              void* d_out, int out_size) {
  const float* pred = (const float*)d_in[0];
  const float* tgt  = (const float*)d_in[1];
  float* out = (float*)d_out;

  chl::k_bin<<<chl::NIMG * chl::SLICES, chl::THR>>>(pred, tgt);
  chl::k_histfinal<<<chl::NIMG, 256>>>(out);
}

// round 4
// speedup vs baseline: 4.3632x; 1.3226x over previous
#include <cuda_runtime.h>
#include <cstdint>

// ColorHistogramLoss — soft 64-bin histogram CDF L1 loss.
// R4: R3 with the gather-base half-bin misalignment fixed
// (sbase = 32j - 144 so taps d=(o-159.5)/32 are centered on bin j).

namespace chl {

constexpr int BINS    = 64;
constexpr int TSUB    = 32;              // subcells per bin
constexpr int NSUB    = BINS * TSUB;     // 2048 subcells over [0,1)
constexpr int NCH     = 12;              // B*C
constexpr int NIMG    = 24;              // 2 tensors * 12 channels
constexpr int PIX     = 65536;           // H*W
constexpr int SLICES  = 16;
constexpr int PIX_BLK = PIX / SLICES;    // 4096
constexpr int THR     = 256;
constexpr int NTAP    = 10;              // 320 taps ~ |d| <= 5 bins
constexpr int PAD     = 160;
constexpr int CSZ     = NSUB + 2 * PAD;  // 2368

__device__ unsigned long long g_acc[NIMG * NSUB];  // packed (cnt<<40)|sum(f*2^20); zero-init
__device__ float g_histf[NIMG * BINS];
__device__ int   g_count;                           // zero-init; reset by last block

__global__ void __launch_bounds__(THR) k_bin(const float* __restrict__ pred,
                                             const float* __restrict__ tgt) {
  __shared__ unsigned long long sh[NSUB];
  int blk   = blockIdx.x;
  int img   = blk / SLICES;             // 0..23
  int slice = blk % SLICES;
  const float* src = (img < NCH ? pred : tgt) + (img % NCH) * PIX + slice * PIX_BLK;

  for (int i = threadIdx.x; i < NSUB; i += THR) sh[i] = 0ULL;
  __syncthreads();

  const float4* p4 = reinterpret_cast<const float4*>(src);
#pragma unroll
  for (int it = 0; it < PIX_BLK / 4 / THR; ++it) {
    float4 v = p4[it * THR + threadIdx.x];
    float xs[4] = {v.x, v.y, v.z, v.w};
#pragma unroll
    for (int k = 0; k < 4; ++k) {
      float su = xs[k] * 2048.0f;          // exact: power-of-2 scale
      int s = (int)su;
      s = max(0, min(NSUB - 1, s));
      float f = su - (float)s;             // in-cell position, [0,1)
      unsigned q = (unsigned)__float2int_rn(f * 1048576.0f);  // f*2^20
      atomicAdd(&sh[s], (1ULL << 40) | (unsigned long long)q);
    }
  }
  __syncthreads();

  unsigned long long* g = g_acc + img * NSUB;
  for (int i = threadIdx.x; i < NSUB; i += THR) {
    unsigned long long v = sh[i];
    if (v) atomicAdd(&g[i], v);
  }
}

// Per-channel soft histogram from subcell moments (fp32); the last block
// to finish computes cdfs + mean |diff| for all channels.
// hist[j] = sum_s  cnt_s * exp(-d^2/2) + sd_s * (1/32)*(-d)exp(-d^2/2),
// d = (s+0.5)/32 - (j+0.5).  s = (32j - 144) + o, o = lane + 32t,
// so d = (o - 159.5)/32, support |d| <~ 5 bins.
__global__ void __launch_bounds__(256) k_histfinal(float* __restrict__ out) {
  __shared__ float cnt_sh[CSZ], sd_sh[CSZ];
  __shared__ float cdf_sh[NIMG][BINS];
  __shared__ float red_sh[8];
  __shared__ int ticket_sh;
  int tid  = threadIdx.x;
  int img  = blockIdx.x;
  int warp = tid >> 5, lane = tid & 31;

  // zero padding regions (160 < 256: one pass each end)
  if (tid < PAD) {
    cnt_sh[tid] = 0.0f;  sd_sh[tid] = 0.0f;
    cnt_sh[CSZ - 1 - tid] = 0.0f;  sd_sh[CSZ - 1 - tid] = 0.0f;
  }

  unsigned long long* g = g_acc + img * NSUB;
  for (int i = tid; i < NSUB; i += 256) {
    unsigned long long v = g[i];
    g[i] = 0ULL;                                   // re-zero for next replay
    float cnt = (float)(unsigned)(v >> 40);
    float lo  = (float)(v & ((1ULL << 40) - 1ULL));
    cnt_sh[i + PAD] = cnt;
    sd_sh[i + PAD]  = lo * 0x1p-20f - cnt * 0.5f;  // sum of (f - 0.5)
  }

  // register-resident Gaussian taps: o = lane + 32t, d = (o - 159.5)/32
  float w[NTAP], wp[NTAP];
#pragma unroll
  for (int t = 0; t < NTAP; ++t) {
    float d = ((float)(lane + 32 * t) - 159.5f) * (1.0f / 32.0f);
    float e = __expf(-0.5f * d * d);
    w[t]  = e;
    wp[t] = -d * e * (1.0f / 32.0f);
  }
  __syncthreads();

  // each warp gathers 8 bins, conflict-free (lanes read consecutive s).
  // padded base index = (32j - 144) + PAD + lane = 32j + 16 + lane.
#pragma unroll
  for (int jj = 0; jj < 8; ++jj) {
    int j = warp * 8 + jj;
    int base = TSUB * j + 16 + lane;
    float a0 = 0.0f, a1 = 0.0f;
#pragma unroll
    for (int t = 0; t < NTAP; ++t) {
      a0 = fmaf(cnt_sh[base + 32 * t], w[t], a0);
      a1 = fmaf(sd_sh[base + 32 * t], wp[t], a1);
    }
    float acc = a0 + a1;
#pragma unroll
    for (int d = 16; d; d >>= 1) acc += __shfl_down_sync(0xffffffffu, acc, d);
    if (lane == 0) g_histf[img * BINS + j] = acc;
  }

  // --- last-block-done ticket ---
  __threadfence();
  __syncthreads();
  if (tid == 0) ticket_sh = atomicAdd(&g_count, 1);
  __syncthreads();
  if (ticket_sh != NIMG - 1) return;

  __threadfence();
  if (tid == 0) g_count = 0;    // reset for next replay

  for (int im = warp; im < NIMG; im += 8) {
    float p0 = g_histf[im * BINS + lane];
    float p1 = g_histf[im * BINS + 32 + lane];
#pragma unroll
    for (int d = 1; d < 32; d <<= 1) {
      float t0 = __shfl_up_sync(0xffffffffu, p0, d);
      float t1 = __shfl_up_sync(0xffffffffu, p1, d);
      if (lane >= d) { p0 += t0; p1 += t1; }
    }
    float half0 = __shfl_sync(0xffffffffu, p0, 31);
    float inv   = __frcp_rn(half0 + __shfl_sync(0xffffffffu, p1, 31) + 1e-8f);
    cdf_sh[im][lane]      = p0 * inv;
    cdf_sh[im][lane + 32] = (half0 + p1) * inv;
  }
  __syncthreads();

  float s = 0.0f;
  for (int i = tid; i < NCH * BINS; i += 256) {
    int ch = i >> 6, jj = i & 63;
    s += fabsf(cdf_sh[ch][jj] - cdf_sh[ch + NCH][jj]);
  }
#pragma unroll
  for (int d = 16; d; d >>= 1) s += __shfl_down_sync(0xffffffffu, s, d);
  if (lane == 0) red_sh[warp] = s;
  __syncthreads();
  if (tid == 0) {
    float tot = 0.0f;
#pragma unroll
    for (int wv = 0; wv < 8; ++wv) tot += red_sh[wv];
    out[0] = tot / (float)(NCH * BINS);
  }
}

}  // namespace chl

extern "C" void kernel_launch(void* const* d_in, const int* in_sizes, int n_in,
                              void* d_out, int out_size) {
  const float* pred = (const float*)d_in[0];
  const float* tgt  = (const float*)d_in[1];
  float* out = (float*)d_out;

  chl::k_bin<<<chl::NIMG * chl::SLICES, chl::THR>>>(pred, tgt);
  chl::k_histfinal<<<chl::NIMG, 256>>>(out);
}